// round 1
// baseline (speedup 1.0000x reference)
#include <cuda_runtime.h>

// LocalKNN: query (64,64,32,32) f32, support (64,5,64,1024) f32 -> out (64,5) f32
// sim[b,w,q,s] = <qn[b,q,:], sn[b,w,s,:]>, top-3 over s, summed over q and k.

#define BATCH   64
#define WAY     5
#define DIM     64
#define NQ      1024
#define NS      1024
#define QT      256     // queries per block (== blockDim.x)
#define SC      128     // support chunk staged in smem
#define SSTR    68      // padded smem row stride in floats (16B aligned)

__global__ void zero_out_kernel(float* out) {
    int i = threadIdx.x;
    if (i < BATCH * WAY) out[i] = 0.0f;
}

__global__ __launch_bounds__(QT, 2)
void localknn_kernel(const float* __restrict__ qf,
                     const float* __restrict__ sf,
                     float* __restrict__ out) {
    __shared__ float smem_s[SC * SSTR];   // [s][d] padded
    __shared__ float s_rinv[SC];
    __shared__ float red[QT / 32];

    const int tid  = threadIdx.x;
    const int qidx = blockIdx.x * QT + tid;
    const int w    = blockIdx.y;
    const int b    = blockIdx.z;

    // ---- load + normalize this thread's query (D strided by NQ, coalesced across threads)
    const float* qp = qf + (size_t)b * DIM * NQ + qidx;
    float q[DIM];
    float ss = 0.0f;
    #pragma unroll
    for (int d = 0; d < DIM; ++d) {
        q[d] = qp[d * NQ];
        ss += q[d] * q[d];
    }
    {
        float rn = rsqrtf(fmaxf(ss, 1e-24f));
        #pragma unroll
        for (int d = 0; d < DIM; ++d) q[d] *= rn;
    }

    float t0 = -1e30f, t1 = -1e30f, t2 = -1e30f;  // running top-3, t0>=t1>=t2

    const float* sp = sf + (size_t)(b * WAY + w) * DIM * NS;

    for (int s0 = 0; s0 < NS; s0 += SC) {
        __syncthreads();
        // ---- stage support chunk: element (d, s) -> smem[s][d]
        #pragma unroll
        for (int i = tid; i < DIM * SC; i += QT) {
            int d = i >> 7;            // i / SC (SC == 128)
            int s = i & (SC - 1);
            smem_s[s * SSTR + d] = sp[d * NS + s0 + s];
        }
        __syncthreads();
        // ---- per-column inverse norms (threads 0..SC-1)
        if (tid < SC) {
            const float4* row = (const float4*)&smem_s[tid * SSTR];
            float acc = 0.0f;
            #pragma unroll
            for (int d4 = 0; d4 < DIM / 4; ++d4) {
                float4 v = row[d4];
                acc += v.x * v.x + v.y * v.y + v.z * v.z + v.w * v.w;
            }
            s_rinv[tid] = rsqrtf(fmaxf(acc, 1e-24f));
        }
        __syncthreads();

        // ---- dot products + top-3 (broadcast LDS.128 reads)
        #pragma unroll 2
        for (int s = 0; s < SC; ++s) {
            const float4* row = (const float4*)&smem_s[s * SSTR];
            float a0 = 0.f, a1 = 0.f, a2 = 0.f, a3 = 0.f;
            #pragma unroll
            for (int d4 = 0; d4 < DIM / 4; d4 += 4) {
                float4 v0 = row[d4 + 0];
                a0 += q[4*(d4+0)+0] * v0.x + q[4*(d4+0)+1] * v0.y
                    + q[4*(d4+0)+2] * v0.z + q[4*(d4+0)+3] * v0.w;
                float4 v1 = row[d4 + 1];
                a1 += q[4*(d4+1)+0] * v1.x + q[4*(d4+1)+1] * v1.y
                    + q[4*(d4+1)+2] * v1.z + q[4*(d4+1)+3] * v1.w;
                float4 v2 = row[d4 + 2];
                a2 += q[4*(d4+2)+0] * v2.x + q[4*(d4+2)+1] * v2.y
                    + q[4*(d4+2)+2] * v2.z + q[4*(d4+2)+3] * v2.w;
                float4 v3 = row[d4 + 3];
                a3 += q[4*(d4+3)+0] * v3.x + q[4*(d4+3)+1] * v3.y
                    + q[4*(d4+3)+2] * v3.z + q[4*(d4+3)+3] * v3.w;
            }
            float sim = ((a0 + a1) + (a2 + a3)) * s_rinv[s];

            // branch-free top-3 insert (5 FMNMX)
            float m0 = fmaxf(t0, sim);
            float l0 = fminf(t0, sim);
            float m1 = fmaxf(t1, l0);
            float l1 = fminf(t1, l0);
            t2 = fmaxf(t2, l1);
            t1 = m1;
            t0 = m0;
        }
    }

    // ---- reduce per-thread (t0+t1+t2) across the block, one atomic per block
    float local = t0 + t1 + t2;
    #pragma unroll
    for (int off = 16; off > 0; off >>= 1)
        local += __shfl_down_sync(0xFFFFFFFFu, local, off);

    int lane = tid & 31, wid = tid >> 5;
    if (lane == 0) red[wid] = local;
    __syncthreads();
    if (wid == 0) {
        float v = (lane < QT / 32) ? red[lane] : 0.0f;
        #pragma unroll
        for (int off = 4; off > 0; off >>= 1)
            v += __shfl_down_sync(0xFFFFFFFFu, v, off);
        if (lane == 0) atomicAdd(&out[b * WAY + w], v);
    }
}

extern "C" void kernel_launch(void* const* d_in, const int* in_sizes, int n_in,
                              void* d_out, int out_size) {
    const float* qf = (const float*)d_in[0];   // (64, 64, 32, 32)
    const float* sf = (const float*)d_in[1];   // (64, 5, 64, 1024)
    float* out = (float*)d_out;                // (64, 5)

    zero_out_kernel<<<1, 512>>>(out);

    dim3 grid(NQ / QT, WAY, BATCH);
    localknn_kernel<<<grid, QT>>>(qf, sf, out);
}

// round 4
// speedup vs baseline: 8.3238x; 8.3238x over previous
#include <cuda_runtime.h>
#include <cuda_fp16.h>
#include <cstdint>

#define BATCH 64
#define WAY   5
#define DIM   64
#define NQ    1024
#define NS    1024
#define QTILE 128
#define SCHUNK 128
#define NCHUNK (NS / SCHUNK)

// fp16 normalized scratch
__device__ __half g_qn[BATCH * NQ * DIM];          // [b][q][d]   8 MB
__device__ __half g_sn[BATCH * WAY * NS * DIM];    // [b][w][s][d] 40 MB

// smem layout (bytes): rows padded to 144B (72 halves) for conflict-free frag loads
#define SROWB 144
#define A_OFF 0
#define B_OFF (QTILE * SROWB)            // 18432
#define BBUF  (SCHUNK * SROWB)           // 18432
#define SMEM_BYTES (B_OFF + 2 * BBUF)    // 55296

__device__ __forceinline__ uint32_t smem_u32(const void* p) {
    uint32_t a;
    asm("{ .reg .u64 t; cvta.to.shared.u64 t, %1; cvt.u32.u64 %0, t; }" : "=r"(a) : "l"(p));
    return a;
}
#define CP16(dst, src) \
    asm volatile("cp.async.cg.shared.global [%0], [%1], 16;" :: "r"(dst), "l"(src))
#define CP_COMMIT() asm volatile("cp.async.commit_group;" ::: "memory")
#define CP_WAIT(n)  asm volatile("cp.async.wait_group %0;" :: "n"(n) : "memory")

#define MMA16816(c0,c1,c2,c3, a0,a1,a2,a3, b0,b1)                               \
    asm volatile("mma.sync.aligned.m16n8k16.row.col.f32.f16.f16.f32 "           \
                 "{%0,%1,%2,%3}, {%4,%5,%6,%7}, {%8,%9}, {%0,%1,%2,%3};"        \
                 : "+f"(c0), "+f"(c1), "+f"(c2), "+f"(c3)                        \
                 : "r"(a0), "r"(a1), "r"(a2), "r"(a3), "r"(b0), "r"(b1))

// branch-free top-3 insert (5 min/max)
#define INS3(t0, t1, t2, s) do {                 \
    float _m0 = fmaxf(t0, s), _l0 = fminf(t0, s);\
    float _m1 = fmaxf(t1, _l0), _l1 = fminf(t1, _l0); \
    t2 = fmaxf(t2, _l1); t1 = _m1; t0 = _m0;     \
} while (0)

__global__ void zero_out_kernel(float* out) {
    int i = threadIdx.x;
    if (i < BATCH * WAY) out[i] = 0.0f;
}

__global__ void __launch_bounds__(256) prep_q(const float* __restrict__ qf) {
    int q = blockIdx.x * 256 + threadIdx.x;
    int b = blockIdx.y;
    const float* src = qf + (size_t)b * DIM * NQ + q;
    float v[DIM]; float ss = 0.0f;
#pragma unroll
    for (int d = 0; d < DIM; ++d) { v[d] = src[(size_t)d * NQ]; ss = fmaf(v[d], v[d], ss); }
    float rn = 1.0f / fmaxf(sqrtf(ss), 1e-12f);
    uint4* dst = (uint4*)(g_qn + ((size_t)b * NQ + q) * DIM);
#pragma unroll
    for (int i = 0; i < 8; ++i) {
        uint32_t u[4];
#pragma unroll
        for (int j = 0; j < 4; ++j) {
            __half2 h = __float22half2_rn(make_float2(v[i*8 + j*2] * rn, v[i*8 + j*2 + 1] * rn));
            u[j] = *(uint32_t*)&h;
        }
        dst[i] = make_uint4(u[0], u[1], u[2], u[3]);
    }
}

__global__ void __launch_bounds__(256) prep_s(const float* __restrict__ sf) {
    int s = blockIdx.x * 256 + threadIdx.x;
    int w = blockIdx.y, b = blockIdx.z;
    size_t bw = (size_t)b * WAY + w;
    const float* src = sf + bw * DIM * NS + s;
    float v[DIM]; float ss = 0.0f;
#pragma unroll
    for (int d = 0; d < DIM; ++d) { v[d] = src[(size_t)d * NS]; ss = fmaf(v[d], v[d], ss); }
    float rn = 1.0f / fmaxf(sqrtf(ss), 1e-12f);
    uint4* dst = (uint4*)(g_sn + (bw * NS + s) * DIM);
#pragma unroll
    for (int i = 0; i < 8; ++i) {
        uint32_t u[4];
#pragma unroll
        for (int j = 0; j < 4; ++j) {
            __half2 h = __float22half2_rn(make_float2(v[i*8 + j*2] * rn, v[i*8 + j*2 + 1] * rn));
            u[j] = *(uint32_t*)&h;
        }
        dst[i] = make_uint4(u[0], u[1], u[2], u[3]);
    }
}

__global__ void __launch_bounds__(256) knn_mma(float* __restrict__ out) {
    extern __shared__ char dsm[];
    __shared__ float red[4];
    __shared__ float xm[4][32][3];   // cross-warpN top-3 exchange: [warpM][row][k]

    const int tid  = threadIdx.x;
    const int lane = tid & 31;
    const int wid  = tid >> 5;
    const int warpM = wid & 3;        // 4 warps along M (32 rows each)
    const int warpN = wid >> 2;       // 2 warps along N (64 cols each)
    const int qt = blockIdx.x, w = blockIdx.y, b = blockIdx.z;

    const uint32_t sbase = smem_u32(dsm);
    const __half* Ag = g_qn + ((size_t)b * NQ + (size_t)qt * QTILE) * DIM;
    const __half* Sg = g_sn + (size_t)(b * WAY + w) * NS * DIM;

    // ---- stage A tile (128 x 64 fp16) via cp.async, group 0
#pragma unroll
    for (int i = 0; i < 4; ++i) {
        int idx = i * 256 + tid;            // 1024 16B segments
        int r = idx >> 3, seg = idx & 7;
        CP16(sbase + A_OFF + r * SROWB + seg * 16, Ag + r * DIM + seg * 8);
    }
    CP_COMMIT();
    // ---- stage S chunk 0 into buf 0, group 1
#pragma unroll
    for (int i = 0; i < 4; ++i) {
        int idx = i * 256 + tid;
        int r = idx >> 3, seg = idx & 7;
        CP16(sbase + B_OFF + r * SROWB + seg * 16, Sg + r * DIM + seg * 8);
    }
    CP_COMMIT();

    CP_WAIT(1);            // A tile ready
    __syncthreads();

    // ---- load A fragments to registers: a[mt][kt][4]
    uint32_t a[2][4][4];
    {
        const int kb = (lane & 3) * 4;     // byte offset of k-pair within 32B k-step
#pragma unroll
        for (int mt = 0; mt < 2; ++mt) {
            int r0 = warpM * 32 + mt * 16 + (lane >> 2);
#pragma unroll
            for (int kt = 0; kt < 4; ++kt) {
                const char* base = dsm + A_OFF + kt * 32 + kb;
                a[mt][kt][0] = *(const uint32_t*)(base + (size_t)r0 * SROWB);
                a[mt][kt][1] = *(const uint32_t*)(base + (size_t)(r0 + 8) * SROWB);
                a[mt][kt][2] = *(const uint32_t*)(base + (size_t)r0 * SROWB + 16);
                a[mt][kt][3] = *(const uint32_t*)(base + (size_t)(r0 + 8) * SROWB + 16);
            }
        }
    }

    float t[4][3];
#pragma unroll
    for (int r = 0; r < 4; ++r) { t[r][0] = -1e30f; t[r][1] = -1e30f; t[r][2] = -1e30f; }

    for (int ch = 0; ch < NCHUNK; ++ch) {
        const int cur = ch & 1;
        __syncthreads();   // all warps done with buffer cur^1 (previous chunk)
        if (ch + 1 < NCHUNK) {
            const __half* src = Sg + (size_t)(ch + 1) * SCHUNK * DIM;
            uint32_t dstb = sbase + B_OFF + (cur ^ 1) * BBUF;
#pragma unroll
            for (int i = 0; i < 4; ++i) {
                int idx = i * 256 + tid;
                int r = idx >> 3, seg = idx & 7;
                CP16(dstb + r * SROWB + seg * 16, src + r * DIM + seg * 8);
            }
            CP_COMMIT();
            CP_WAIT(1);    // chunk ch ready (ch+1 may be in flight)
        } else {
            CP_WAIT(0);
        }
        __syncthreads();

        const char* bp = dsm + B_OFF + cur * BBUF;
        const int kb = (lane & 3) * 4;
#pragma unroll 1
        for (int nt = 0; nt < 8; ++nt) {
            float c[8] = {0.f, 0.f, 0.f, 0.f, 0.f, 0.f, 0.f, 0.f};
            const char* brow = bp + (size_t)(warpN * 64 + nt * 8 + (lane >> 2)) * SROWB + kb;
#pragma unroll
            for (int kt = 0; kt < 4; ++kt) {
                uint32_t b0 = *(const uint32_t*)(brow + kt * 32);
                uint32_t b1 = *(const uint32_t*)(brow + kt * 32 + 16);
                MMA16816(c[0], c[1], c[2], c[3], a[0][kt][0], a[0][kt][1], a[0][kt][2], a[0][kt][3], b0, b1);
                MMA16816(c[4], c[5], c[6], c[7], a[1][kt][0], a[1][kt][1], a[1][kt][2], a[1][kt][3], b0, b1);
            }
            // rows: t[0]=(mt0,+0) t[1]=(mt0,+8) t[2]=(mt1,+0) t[3]=(mt1,+8)
            INS3(t[0][0], t[0][1], t[0][2], c[0]);
            INS3(t[0][0], t[0][1], t[0][2], c[1]);
            INS3(t[1][0], t[1][1], t[1][2], c[2]);
            INS3(t[1][0], t[1][1], t[1][2], c[3]);
            INS3(t[2][0], t[2][1], t[2][2], c[4]);
            INS3(t[2][0], t[2][1], t[2][2], c[5]);
            INS3(t[3][0], t[3][1], t[3][2], c[6]);
            INS3(t[3][0], t[3][1], t[3][2], c[7]);
        }
    }

    // ---- merge top-3 across the 4 lanes (lane%4) that share each row
#pragma unroll
    for (int r = 0; r < 4; ++r) {
#pragma unroll
        for (int d = 1; d <= 2; d <<= 1) {
            float r0 = __shfl_xor_sync(0xFFFFFFFFu, t[r][0], d);
            float r1 = __shfl_xor_sync(0xFFFFFFFFu, t[r][1], d);
            float r2 = __shfl_xor_sync(0xFFFFFFFFu, t[r][2], d);
            INS3(t[r][0], t[r][1], t[r][2], r0);
            INS3(t[r][0], t[r][1], t[r][2], r1);
            INS3(t[r][0], t[r][1], t[r][2], r2);
        }
    }

    // ---- merge top-3 across warpN halves (each kept top-3 of its 512 columns;
    //      the true top-3 over all 1024 columns is top-3 of the union)
    const int gid = lane >> 2;
    if (warpN == 1 && (lane & 3) == 0) {
#pragma unroll
        for (int r = 0; r < 4; ++r) {
            int row = (r >> 1) * 16 + (r & 1) * 8 + gid;
            xm[warpM][row][0] = t[r][0];
            xm[warpM][row][1] = t[r][1];
            xm[warpM][row][2] = t[r][2];
        }
    }
    __syncthreads();

    if (warpN == 0) {
        float local = 0.0f;
        if ((lane & 3) == 0) {
#pragma unroll
            for (int r = 0; r < 4; ++r) {
                int row = (r >> 1) * 16 + (r & 1) * 8 + gid;
                INS3(t[r][0], t[r][1], t[r][2], xm[warpM][row][0]);
                INS3(t[r][0], t[r][1], t[r][2], xm[warpM][row][1]);
                INS3(t[r][0], t[r][1], t[r][2], xm[warpM][row][2]);
                local += t[r][0] + t[r][1] + t[r][2];
            }
        }
#pragma unroll
        for (int off = 16; off > 0; off >>= 1)
            local += __shfl_down_sync(0xFFFFFFFFu, local, off);
        if (lane == 0) red[warpM] = local;
    }
    __syncthreads();
    if (tid == 0) {
        atomicAdd(&out[b * WAY + w], red[0] + red[1] + red[2] + red[3]);
    }
}

extern "C" void kernel_launch(void* const* d_in, const int* in_sizes, int n_in,
                              void* d_out, int out_size) {
    const float* qf = (const float*)d_in[0];   // (64, 64, 32, 32)
    const float* sf = (const float*)d_in[1];   // (64, 5, 64, 1024)
    float* out = (float*)d_out;                // (64, 5)

    cudaFuncSetAttribute(knn_mma, cudaFuncAttributeMaxDynamicSharedMemorySize, SMEM_BYTES);

    zero_out_kernel<<<1, 512>>>(out);
    prep_q<<<dim3(NQ / 256, BATCH), 256>>>(qf);
    prep_s<<<dim3(NS / 256, WAY, BATCH), 256>>>(sf);
    knn_mma<<<dim3(NQ / QTILE, WAY, BATCH), 256, SMEM_BYTES>>>(out);
}

// round 5
// speedup vs baseline: 8.6838x; 1.0432x over previous
#include <cuda_runtime.h>
#include <cuda_fp16.h>
#include <cstdint>

#define BATCH 64
#define WAY   5
#define DIM   64
#define NQ    1024
#define NS    1024
#define QTILE 128
#define SCHUNK 128
#define NCHUNK (NS / SCHUNK)

// fp16 normalized scratch
__device__ __half g_qn[BATCH * NQ * DIM];          // [b][q][d]   8 MB
__device__ __half g_sn[BATCH * WAY * NS * DIM];    // [b][w][s][d] 40 MB

// smem layout (bytes): rows padded to 144B (72 halves) for conflict-free frag loads
#define SROWB 144
#define A_OFF 0
#define B_OFF (QTILE * SROWB)            // 18432
#define BBUF  (SCHUNK * SROWB)           // 18432
#define SMEM_BYTES (B_OFF + 2 * BBUF)    // 55296

__device__ __forceinline__ uint32_t smem_u32(const void* p) {
    uint32_t a;
    asm("{ .reg .u64 t; cvta.to.shared.u64 t, %1; cvt.u32.u64 %0, t; }" : "=r"(a) : "l"(p));
    return a;
}
#define CP16(dst, src) \
    asm volatile("cp.async.cg.shared.global [%0], [%1], 16;" :: "r"(dst), "l"(src))
#define CP_COMMIT() asm volatile("cp.async.commit_group;" ::: "memory")
#define CP_WAIT(n)  asm volatile("cp.async.wait_group %0;" :: "n"(n) : "memory")

#define MMA16816(c0,c1,c2,c3, a0,a1,a2,a3, b0,b1)                               \
    asm volatile("mma.sync.aligned.m16n8k16.row.col.f32.f16.f16.f32 "           \
                 "{%0,%1,%2,%3}, {%4,%5,%6,%7}, {%8,%9}, {%0,%1,%2,%3};"        \
                 : "+f"(c0), "+f"(c1), "+f"(c2), "+f"(c3)                        \
                 : "r"(a0), "r"(a1), "r"(a2), "r"(a3), "r"(b0), "r"(b1))

// branch-free top-3 insert, fp32 (5 min/max)
#define INS3(t0, t1, t2, s) do {                 \
    float _m0 = fmaxf(t0, s), _l0 = fminf(t0, s);\
    float _m1 = fmaxf(t1, _l0), _l1 = fminf(t1, _l0); \
    t2 = fmaxf(t2, _l1); t1 = _m1; t0 = _m0;     \
} while (0)

// branch-free top-3 insert, half2 (2 independent streams per op)
#define INS3H(t0, t1, t2, s) do {                          \
    __half2 _m0 = __hmax2(t0, s), _l0 = __hmin2(t0, s);    \
    __half2 _m1 = __hmax2(t1, _l0), _l1 = __hmin2(t1, _l0);\
    t2 = __hmax2(t2, _l1); t1 = _m1; t0 = _m0;             \
} while (0)

__global__ void zero_out_kernel(float* out) {
    int i = threadIdx.x;
    if (i < BATCH * WAY) out[i] = 0.0f;
}

__global__ void __launch_bounds__(256) prep_q(const float* __restrict__ qf) {
    int q = blockIdx.x * 256 + threadIdx.x;
    int b = blockIdx.y;
    const float* src = qf + (size_t)b * DIM * NQ + q;
    float v[DIM]; float ss = 0.0f;
#pragma unroll
    for (int d = 0; d < DIM; ++d) { v[d] = src[(size_t)d * NQ]; ss = fmaf(v[d], v[d], ss); }
    float rn = 1.0f / fmaxf(sqrtf(ss), 1e-12f);
    uint4* dst = (uint4*)(g_qn + ((size_t)b * NQ + q) * DIM);
#pragma unroll
    for (int i = 0; i < 8; ++i) {
        uint32_t u[4];
#pragma unroll
        for (int j = 0; j < 4; ++j) {
            __half2 h = __float22half2_rn(make_float2(v[i*8 + j*2] * rn, v[i*8 + j*2 + 1] * rn));
            u[j] = *(uint32_t*)&h;
        }
        dst[i] = make_uint4(u[0], u[1], u[2], u[3]);
    }
}

__global__ void __launch_bounds__(256) prep_s(const float* __restrict__ sf) {
    int s = blockIdx.x * 256 + threadIdx.x;
    int w = blockIdx.y, b = blockIdx.z;
    size_t bw = (size_t)b * WAY + w;
    const float* src = sf + bw * DIM * NS + s;
    float v[DIM]; float ss = 0.0f;
#pragma unroll
    for (int d = 0; d < DIM; ++d) { v[d] = src[(size_t)d * NS]; ss = fmaf(v[d], v[d], ss); }
    float rn = 1.0f / fmaxf(sqrtf(ss), 1e-12f);
    uint4* dst = (uint4*)(g_sn + (bw * NS + s) * DIM);
#pragma unroll
    for (int i = 0; i < 8; ++i) {
        uint32_t u[4];
#pragma unroll
        for (int j = 0; j < 4; ++j) {
            __half2 h = __float22half2_rn(make_float2(v[i*8 + j*2] * rn, v[i*8 + j*2 + 1] * rn));
            u[j] = *(uint32_t*)&h;
        }
        dst[i] = make_uint4(u[0], u[1], u[2], u[3]);
    }
}

__global__ void __launch_bounds__(256) knn_mma(float* __restrict__ out) {
    extern __shared__ char dsm[];
    __shared__ float red[4];
    __shared__ float xm[4][32][3];   // cross-warpN top-3 exchange: [warpM][row][k]

    const int tid  = threadIdx.x;
    const int lane = tid & 31;
    const int wid  = tid >> 5;
    const int warpM = wid & 3;        // 4 warps along M (32 rows each)
    const int warpN = wid >> 2;       // 2 warps along N (64 cols each)
    const int qt = blockIdx.x, w = blockIdx.y, b = blockIdx.z;

    const uint32_t sbase = smem_u32(dsm);
    const __half* Ag = g_qn + ((size_t)b * NQ + (size_t)qt * QTILE) * DIM;
    const __half* Sg = g_sn + (size_t)(b * WAY + w) * NS * DIM;

    // ---- stage A tile (128 x 64 fp16) via cp.async, group 0
#pragma unroll
    for (int i = 0; i < 4; ++i) {
        int idx = i * 256 + tid;            // 1024 16B segments
        int r = idx >> 3, seg = idx & 7;
        CP16(sbase + A_OFF + r * SROWB + seg * 16, Ag + r * DIM + seg * 8);
    }
    CP_COMMIT();
    // ---- stage S chunk 0 into buf 0, group 1
#pragma unroll
    for (int i = 0; i < 4; ++i) {
        int idx = i * 256 + tid;
        int r = idx >> 3, seg = idx & 7;
        CP16(sbase + B_OFF + r * SROWB + seg * 16, Sg + r * DIM + seg * 8);
    }
    CP_COMMIT();

    CP_WAIT(1);            // A tile ready
    __syncthreads();

    // ---- load A fragments to registers: a[mt][kt][4]
    uint32_t a[2][4][4];
    {
        const int kb = (lane & 3) * 4;     // byte offset of k-pair within 32B k-step
#pragma unroll
        for (int mt = 0; mt < 2; ++mt) {
            int r0 = warpM * 32 + mt * 16 + (lane >> 2);
#pragma unroll
            for (int kt = 0; kt < 4; ++kt) {
                const char* base = dsm + A_OFF + kt * 32 + kb;
                a[mt][kt][0] = *(const uint32_t*)(base + (size_t)r0 * SROWB);
                a[mt][kt][1] = *(const uint32_t*)(base + (size_t)(r0 + 8) * SROWB);
                a[mt][kt][2] = *(const uint32_t*)(base + (size_t)r0 * SROWB + 16);
                a[mt][kt][3] = *(const uint32_t*)(base + (size_t)(r0 + 8) * SROWB + 16);
            }
        }
    }

    // half2 top-3 streams: t[r][k], r = (mt, rowhalf); halves = column-parity streams
    const __half2 NEGINF = __halves2half2(__ushort_as_half(0xFC00), __ushort_as_half(0xFC00));
    __half2 t[4][3];
#pragma unroll
    for (int r = 0; r < 4; ++r) { t[r][0] = NEGINF; t[r][1] = NEGINF; t[r][2] = NEGINF; }

    for (int ch = 0; ch < NCHUNK; ++ch) {
        const int cur = ch & 1;
        __syncthreads();   // all warps done with buffer cur^1 (previous chunk)
        if (ch + 1 < NCHUNK) {
            const __half* src = Sg + (size_t)(ch + 1) * SCHUNK * DIM;
            uint32_t dstb = sbase + B_OFF + (cur ^ 1) * BBUF;
#pragma unroll
            for (int i = 0; i < 4; ++i) {
                int idx = i * 256 + tid;
                int r = idx >> 3, seg = idx & 7;
                CP16(dstb + r * SROWB + seg * 16, src + r * DIM + seg * 8);
            }
            CP_COMMIT();
            CP_WAIT(1);    // chunk ch ready (ch+1 may be in flight)
        } else {
            CP_WAIT(0);
        }
        __syncthreads();

        const char* bp = dsm + B_OFF + cur * BBUF;
        const int kb = (lane & 3) * 4;
#pragma unroll 1
        for (int nt = 0; nt < 8; ++nt) {
            float c[8] = {0.f, 0.f, 0.f, 0.f, 0.f, 0.f, 0.f, 0.f};
            const char* brow = bp + (size_t)(warpN * 64 + nt * 8 + (lane >> 2)) * SROWB + kb;
#pragma unroll
            for (int kt = 0; kt < 4; ++kt) {
                uint32_t b0 = *(const uint32_t*)(brow + kt * 32);
                uint32_t b1 = *(const uint32_t*)(brow + kt * 32 + 16);
                MMA16816(c[0], c[1], c[2], c[3], a[0][kt][0], a[0][kt][1], a[0][kt][2], a[0][kt][3], b0, b1);
                MMA16816(c[4], c[5], c[6], c[7], a[1][kt][0], a[1][kt][1], a[1][kt][2], a[1][kt][3], b0, b1);
            }
            // pack column-pairs into half2, insert into per-row streams
            __half2 p0 = __floats2half2_rn(c[0], c[1]);   // (mt0, +0)
            __half2 p1 = __floats2half2_rn(c[2], c[3]);   // (mt0, +8)
            __half2 p2 = __floats2half2_rn(c[4], c[5]);   // (mt1, +0)
            __half2 p3 = __floats2half2_rn(c[6], c[7]);   // (mt1, +8)
            INS3H(t[0][0], t[0][1], t[0][2], p0);
            INS3H(t[1][0], t[1][1], t[1][2], p1);
            INS3H(t[2][0], t[2][1], t[2][2], p2);
            INS3H(t[3][0], t[3][1], t[3][2], p3);
        }
    }

    // ---- merge top-3 across the 4 lanes (lane%4) that share each row (half2 domain)
#pragma unroll
    for (int r = 0; r < 4; ++r) {
#pragma unroll
        for (int d = 1; d <= 2; d <<= 1) {
            __half2 r0, r1, r2;
            *(uint32_t*)&r0 = __shfl_xor_sync(0xFFFFFFFFu, *(uint32_t*)&t[r][0], d);
            *(uint32_t*)&r1 = __shfl_xor_sync(0xFFFFFFFFu, *(uint32_t*)&t[r][1], d);
            *(uint32_t*)&r2 = __shfl_xor_sync(0xFFFFFFFFu, *(uint32_t*)&t[r][2], d);
            INS3H(t[r][0], t[r][1], t[r][2], r0);
            INS3H(t[r][0], t[r][1], t[r][2], r1);
            INS3H(t[r][0], t[r][1], t[r][2], r2);
        }
    }

    // ---- unpack halves (column-parity streams) and merge to per-row f32 top-3
    float f[4][3];
#pragma unroll
    for (int r = 0; r < 4; ++r) {
        f[r][0] = -1e30f; f[r][1] = -1e30f; f[r][2] = -1e30f;
#pragma unroll
        for (int k = 0; k < 3; ++k) {
            INS3(f[r][0], f[r][1], f[r][2], __low2float(t[r][k]));
            INS3(f[r][0], f[r][1], f[r][2], __high2float(t[r][k]));
        }
    }

    // ---- merge top-3 across warpN halves (each covered 512 of 1024 columns)
    const int gid = lane >> 2;
    if (warpN == 1 && (lane & 3) == 0) {
#pragma unroll
        for (int r = 0; r < 4; ++r) {
            int row = (r >> 1) * 16 + (r & 1) * 8 + gid;
            xm[warpM][row][0] = f[r][0];
            xm[warpM][row][1] = f[r][1];
            xm[warpM][row][2] = f[r][2];
        }
    }
    __syncthreads();

    if (warpN == 0) {
        float local = 0.0f;
        if ((lane & 3) == 0) {
#pragma unroll
            for (int r = 0; r < 4; ++r) {
                int row = (r >> 1) * 16 + (r & 1) * 8 + gid;
                INS3(f[r][0], f[r][1], f[r][2], xm[warpM][row][0]);
                INS3(f[r][0], f[r][1], f[r][2], xm[warpM][row][1]);
                INS3(f[r][0], f[r][1], f[r][2], xm[warpM][row][2]);
                local += f[r][0] + f[r][1] + f[r][2];
            }
        }
#pragma unroll
        for (int off = 16; off > 0; off >>= 1)
            local += __shfl_down_sync(0xFFFFFFFFu, local, off);
        if (lane == 0) red[warpM] = local;
    }
    __syncthreads();
    if (tid == 0) {
        atomicAdd(&out[b * WAY + w], red[0] + red[1] + red[2] + red[3]);
    }
}

extern "C" void kernel_launch(void* const* d_in, const int* in_sizes, int n_in,
                              void* d_out, int out_size) {
    const float* qf = (const float*)d_in[0];   // (64, 64, 32, 32)
    const float* sf = (const float*)d_in[1];   // (64, 5, 64, 1024)
    float* out = (float*)d_out;                // (64, 5)

    cudaFuncSetAttribute(knn_mma, cudaFuncAttributeMaxDynamicSharedMemorySize, SMEM_BYTES);

    zero_out_kernel<<<1, 512>>>(out);
    prep_q<<<dim3(NQ / 256, BATCH), 256>>>(qf);
    prep_s<<<dim3(NS / 256, WAY, BATCH), 256>>>(sf);
    knn_mma<<<dim3(NQ / QTILE, WAY, BATCH), 256, SMEM_BYTES>>>(out);
}

// round 6
// speedup vs baseline: 9.5201x; 1.0963x over previous
#include <cuda_runtime.h>
#include <cuda_fp16.h>
#include <cstdint>

#define BATCH 64
#define WAY   5
#define DIM   64
#define NQ    1024
#define NS    1024
#define QTILE 128
#define SCHUNK 128
#define NCHUNK (NS / SCHUNK)

// fp16 normalized scratch
__device__ __half g_qn[BATCH * NQ * DIM];          // [b][q][d]   8 MB
__device__ __half g_sn[BATCH * WAY * NS * DIM];    // [b][w][s][d] 40 MB

// smem layout (bytes): rows padded to 144B (72 halves) for conflict-free frag loads
#define SROWB 144
#define A_OFF 0
#define B_OFF (QTILE * SROWB)            // 18432
#define BBUF  (SCHUNK * SROWB)           // 18432
#define SMEM_BYTES (B_OFF + 2 * BBUF)    // 55296

__device__ __forceinline__ uint32_t smem_u32(const void* p) {
    uint32_t a;
    asm("{ .reg .u64 t; cvta.to.shared.u64 t, %1; cvt.u32.u64 %0, t; }" : "=r"(a) : "l"(p));
    return a;
}
#define CP16(dst, src) \
    asm volatile("cp.async.cg.shared.global [%0], [%1], 16;" :: "r"(dst), "l"(src))
#define CP_COMMIT() asm volatile("cp.async.commit_group;" ::: "memory")
#define CP_WAIT(n)  asm volatile("cp.async.wait_group %0;" :: "n"(n) : "memory")

// m16n8k16, fp16 accumulate: D/C = 2 b32 regs (2 adjacent cols per reg)
#define MMA16816H(d0,d1, a0,a1,a2,a3, b0,b1)                                    \
    asm volatile("mma.sync.aligned.m16n8k16.row.col.f16.f16.f16.f16 "           \
                 "{%0,%1}, {%2,%3,%4,%5}, {%6,%7}, {%0,%1};"                    \
                 : "+r"(d0), "+r"(d1)                                            \
                 : "r"(a0), "r"(a1), "r"(a2), "r"(a3), "r"(b0), "r"(b1))

// branch-free top-3 insert, fp32 (5 min/max)
#define INS3(t0, t1, t2, s) do {                 \
    float _m0 = fmaxf(t0, s), _l0 = fminf(t0, s);\
    float _m1 = fmaxf(t1, _l0), _l1 = fminf(t1, _l0); \
    t2 = fmaxf(t2, _l1); t1 = _m1; t0 = _m0;     \
} while (0)

// branch-free top-3 insert, half2 (2 independent streams per op)
#define INS3H(t0, t1, t2, s) do {                          \
    __half2 _m0 = __hmax2(t0, s), _l0 = __hmin2(t0, s);    \
    __half2 _m1 = __hmax2(t1, _l0), _l1 = __hmin2(t1, _l0);\
    t2 = __hmax2(t2, _l1); t1 = _m1; t0 = _m0;             \
} while (0)

__global__ void zero_out_kernel(float* out) {
    int i = threadIdx.x;
    if (i < BATCH * WAY) out[i] = 0.0f;
}

__global__ void __launch_bounds__(256) prep_q(const float* __restrict__ qf) {
    int q = blockIdx.x * 256 + threadIdx.x;
    int b = blockIdx.y;
    const float* src = qf + (size_t)b * DIM * NQ + q;
    float v[DIM]; float ss = 0.0f;
#pragma unroll
    for (int d = 0; d < DIM; ++d) { v[d] = src[(size_t)d * NQ]; ss = fmaf(v[d], v[d], ss); }
    float rn = 1.0f / fmaxf(sqrtf(ss), 1e-12f);
    uint4* dst = (uint4*)(g_qn + ((size_t)b * NQ + q) * DIM);
#pragma unroll
    for (int i = 0; i < 8; ++i) {
        uint32_t u[4];
#pragma unroll
        for (int j = 0; j < 4; ++j) {
            __half2 h = __float22half2_rn(make_float2(v[i*8 + j*2] * rn, v[i*8 + j*2 + 1] * rn));
            u[j] = *(uint32_t*)&h;
        }
        dst[i] = make_uint4(u[0], u[1], u[2], u[3]);
    }
}

__global__ void __launch_bounds__(256) prep_s(const float* __restrict__ sf) {
    int s = blockIdx.x * 256 + threadIdx.x;
    int w = blockIdx.y, b = blockIdx.z;
    size_t bw = (size_t)b * WAY + w;
    const float* src = sf + bw * DIM * NS + s;
    float v[DIM]; float ss = 0.0f;
#pragma unroll
    for (int d = 0; d < DIM; ++d) { v[d] = src[(size_t)d * NS]; ss = fmaf(v[d], v[d], ss); }
    float rn = 1.0f / fmaxf(sqrtf(ss), 1e-12f);
    uint4* dst = (uint4*)(g_sn + (bw * NS + s) * DIM);
#pragma unroll
    for (int i = 0; i < 8; ++i) {
        uint32_t u[4];
#pragma unroll
        for (int j = 0; j < 4; ++j) {
            __half2 h = __float22half2_rn(make_float2(v[i*8 + j*2] * rn, v[i*8 + j*2 + 1] * rn));
            u[j] = *(uint32_t*)&h;
        }
        dst[i] = make_uint4(u[0], u[1], u[2], u[3]);
    }
}

__global__ void __launch_bounds__(256) knn_mma(float* __restrict__ out) {
    extern __shared__ char dsm[];
    __shared__ float red[4];
    __shared__ float xm[4][32][3];   // cross-warpN top-3 exchange: [warpM][row][k]

    const int tid  = threadIdx.x;
    const int lane = tid & 31;
    const int wid  = tid >> 5;
    const int warpM = wid & 3;        // 4 warps along M (32 rows each)
    const int warpN = wid >> 2;       // 2 warps along N (64 cols each)
    const int qt = blockIdx.x, w = blockIdx.y, b = blockIdx.z;

    const uint32_t sbase = smem_u32(dsm);
    const __half* Ag = g_qn + ((size_t)b * NQ + (size_t)qt * QTILE) * DIM;
    const __half* Sg = g_sn + (size_t)(b * WAY + w) * NS * DIM;

    // ---- stage A tile (128 x 64 fp16) via cp.async, group 0
#pragma unroll
    for (int i = 0; i < 4; ++i) {
        int idx = i * 256 + tid;            // 1024 16B segments
        int r = idx >> 3, seg = idx & 7;
        CP16(sbase + A_OFF + r * SROWB + seg * 16, Ag + r * DIM + seg * 8);
    }
    CP_COMMIT();
    // ---- stage S chunk 0 into buf 0, group 1
#pragma unroll
    for (int i = 0; i < 4; ++i) {
        int idx = i * 256 + tid;
        int r = idx >> 3, seg = idx & 7;
        CP16(sbase + B_OFF + r * SROWB + seg * 16, Sg + r * DIM + seg * 8);
    }
    CP_COMMIT();

    CP_WAIT(1);            // A tile ready
    __syncthreads();

    // ---- load A fragments to registers: a[mt][kt][4]
    uint32_t a[2][4][4];
    {
        const int kb = (lane & 3) * 4;     // byte offset of k-pair within 32B k-step
#pragma unroll
        for (int mt = 0; mt < 2; ++mt) {
            int r0 = warpM * 32 + mt * 16 + (lane >> 2);
#pragma unroll
            for (int kt = 0; kt < 4; ++kt) {
                const char* base = dsm + A_OFF + kt * 32 + kb;
                a[mt][kt][0] = *(const uint32_t*)(base + (size_t)r0 * SROWB);
                a[mt][kt][1] = *(const uint32_t*)(base + (size_t)(r0 + 8) * SROWB);
                a[mt][kt][2] = *(const uint32_t*)(base + (size_t)r0 * SROWB + 16);
                a[mt][kt][3] = *(const uint32_t*)(base + (size_t)(r0 + 8) * SROWB + 16);
            }
        }
    }

    // half2 top-3 streams: t[r][k], r = (mt, rowhalf); halves = column-parity streams
    const __half2 NEGINF = __halves2half2(__ushort_as_half(0xFC00), __ushort_as_half(0xFC00));
    __half2 t[4][3];
#pragma unroll
    for (int r = 0; r < 4; ++r) { t[r][0] = NEGINF; t[r][1] = NEGINF; t[r][2] = NEGINF; }

    for (int ch = 0; ch < NCHUNK; ++ch) {
        const int cur = ch & 1;
        __syncthreads();   // all warps done with buffer cur^1 (previous chunk)
        if (ch + 1 < NCHUNK) {
            const __half* src = Sg + (size_t)(ch + 1) * SCHUNK * DIM;
            uint32_t dstb = sbase + B_OFF + (cur ^ 1) * BBUF;
#pragma unroll
            for (int i = 0; i < 4; ++i) {
                int idx = i * 256 + tid;
                int r = idx >> 3, seg = idx & 7;
                CP16(dstb + r * SROWB + seg * 16, src + r * DIM + seg * 8);
            }
            CP_COMMIT();
            CP_WAIT(1);    // chunk ch ready (ch+1 may be in flight)
        } else {
            CP_WAIT(0);
        }
        __syncthreads();

        const char* bp = dsm + B_OFF + cur * BBUF;
        const int kb = (lane & 3) * 4;
        // 2 nt per iteration -> 4 independent MMA accumulate chains
#pragma unroll 1
        for (int nt = 0; nt < 8; nt += 2) {
            uint32_t d00 = 0, d01 = 0;   // nt+0, mt0
            uint32_t d02 = 0, d03 = 0;   // nt+0, mt1
            uint32_t d10 = 0, d11 = 0;   // nt+1, mt0
            uint32_t d12 = 0, d13 = 0;   // nt+1, mt1
            const char* brow0 = bp + (size_t)(warpN * 64 + nt * 8 + (lane >> 2)) * SROWB + kb;
            const char* brow1 = brow0 + 8 * SROWB;
#pragma unroll
            for (int kt = 0; kt < 4; ++kt) {
                uint32_t b00 = *(const uint32_t*)(brow0 + kt * 32);
                uint32_t b01 = *(const uint32_t*)(brow0 + kt * 32 + 16);
                uint32_t b10 = *(const uint32_t*)(brow1 + kt * 32);
                uint32_t b11 = *(const uint32_t*)(brow1 + kt * 32 + 16);
                MMA16816H(d00, d01, a[0][kt][0], a[0][kt][1], a[0][kt][2], a[0][kt][3], b00, b01);
                MMA16816H(d02, d03, a[1][kt][0], a[1][kt][1], a[1][kt][2], a[1][kt][3], b00, b01);
                MMA16816H(d10, d11, a[0][kt][0], a[0][kt][1], a[0][kt][2], a[0][kt][3], b10, b11);
                MMA16816H(d12, d13, a[1][kt][0], a[1][kt][1], a[1][kt][2], a[1][kt][3], b10, b11);
            }
            // D regs are half2 of adjacent columns: feed tournament directly
            INS3H(t[0][0], t[0][1], t[0][2], *(__half2*)&d00);
            INS3H(t[1][0], t[1][1], t[1][2], *(__half2*)&d01);
            INS3H(t[2][0], t[2][1], t[2][2], *(__half2*)&d02);
            INS3H(t[3][0], t[3][1], t[3][2], *(__half2*)&d03);
            INS3H(t[0][0], t[0][1], t[0][2], *(__half2*)&d10);
            INS3H(t[1][0], t[1][1], t[1][2], *(__half2*)&d11);
            INS3H(t[2][0], t[2][1], t[2][2], *(__half2*)&d12);
            INS3H(t[3][0], t[3][1], t[3][2], *(__half2*)&d13);
        }
    }

    // ---- merge top-3 across the 4 lanes (lane%4) that share each row (half2 domain)
#pragma unroll
    for (int r = 0; r < 4; ++r) {
#pragma unroll
        for (int d = 1; d <= 2; d <<= 1) {
            __half2 r0, r1, r2;
            *(uint32_t*)&r0 = __shfl_xor_sync(0xFFFFFFFFu, *(uint32_t*)&t[r][0], d);
            *(uint32_t*)&r1 = __shfl_xor_sync(0xFFFFFFFFu, *(uint32_t*)&t[r][1], d);
            *(uint32_t*)&r2 = __shfl_xor_sync(0xFFFFFFFFu, *(uint32_t*)&t[r][2], d);
            INS3H(t[r][0], t[r][1], t[r][2], r0);
            INS3H(t[r][0], t[r][1], t[r][2], r1);
            INS3H(t[r][0], t[r][1], t[r][2], r2);
        }
    }

    // ---- unpack halves (column-parity streams) and merge to per-row f32 top-3
    float f[4][3];
#pragma unroll
    for (int r = 0; r < 4; ++r) {
        f[r][0] = -1e30f; f[r][1] = -1e30f; f[r][2] = -1e30f;
#pragma unroll
        for (int k = 0; k < 3; ++k) {
            INS3(f[r][0], f[r][1], f[r][2], __low2float(t[r][k]));
            INS3(f[r][0], f[r][1], f[r][2], __high2float(t[r][k]));
        }
    }

    // ---- merge top-3 across warpN halves (each covered 512 of 1024 columns)
    const int gid = lane >> 2;
    if (warpN == 1 && (lane & 3) == 0) {
#pragma unroll
        for (int r = 0; r < 4; ++r) {
            int row = (r >> 1) * 16 + (r & 1) * 8 + gid;
            xm[warpM][row][0] = f[r][0];
            xm[warpM][row][1] = f[r][1];
            xm[warpM][row][2] = f[r][2];
        }
    }
    __syncthreads();

    if (warpN == 0) {
        float local = 0.0f;
        if ((lane & 3) == 0) {
#pragma unroll
            for (int r = 0; r < 4; ++r) {
                int row = (r >> 1) * 16 + (r & 1) * 8 + gid;
                INS3(f[r][0], f[r][1], f[r][2], xm[warpM][row][0]);
                INS3(f[r][0], f[r][1], f[r][2], xm[warpM][row][1]);
                INS3(f[r][0], f[r][1], f[r][2], xm[warpM][row][2]);
                local += f[r][0] + f[r][1] + f[r][2];
            }
        }
#pragma unroll
        for (int off = 16; off > 0; off >>= 1)
            local += __shfl_down_sync(0xFFFFFFFFu, local, off);
        if (lane == 0) red[warpM] = local;
    }
    __syncthreads();
    if (tid == 0) {
        atomicAdd(&out[b * WAY + w], red[0] + red[1] + red[2] + red[3]);
    }
}

extern "C" void kernel_launch(void* const* d_in, const int* in_sizes, int n_in,
                              void* d_out, int out_size) {
    const float* qf = (const float*)d_in[0];   // (64, 64, 32, 32)
    const float* sf = (const float*)d_in[1];   // (64, 5, 64, 1024)
    float* out = (float*)d_out;                // (64, 5)

    cudaFuncSetAttribute(knn_mma, cudaFuncAttributeMaxDynamicSharedMemorySize, SMEM_BYTES);

    zero_out_kernel<<<1, 512>>>(out);
    prep_q<<<dim3(NQ / 256, BATCH), 256>>>(qf);
    prep_s<<<dim3(NS / 256, WAY, BATCH), 256>>>(sf);
    knn_mma<<<dim3(NQ / QTILE, WAY, BATCH), 256, SMEM_BYTES>>>(out);
}

// round 7
// speedup vs baseline: 9.6361x; 1.0122x over previous
#include <cuda_runtime.h>
#include <cuda_fp16.h>
#include <cstdint>

#define BATCH 64
#define WAY   5
#define DIM   64
#define NQ    1024
#define NS    1024
#define QTILE 128
#define SCHUNK 128
#define NCHUNK (NS / SCHUNK)

// fp16 normalized scratch
__device__ __half g_qn[BATCH * NQ * DIM];          // [b][q][d]   8 MB
__device__ __half g_sn[BATCH * WAY * NS * DIM];    // [b][w][s][d] 40 MB

// smem layout (bytes): rows padded to 144B (72 halves) for conflict-free frag loads
#define SROWB 144
#define A_OFF 0
#define B_OFF (QTILE * SROWB)            // 18432
#define BBUF  (SCHUNK * SROWB)           // 18432
#define SMEM_BYTES (B_OFF + 2 * BBUF)    // 55296

__device__ __forceinline__ uint32_t smem_u32(const void* p) {
    uint32_t a;
    asm("{ .reg .u64 t; cvta.to.shared.u64 t, %1; cvt.u32.u64 %0, t; }" : "=r"(a) : "l"(p));
    return a;
}
#define CP16(dst, src) \
    asm volatile("cp.async.cg.shared.global [%0], [%1], 16;" :: "r"(dst), "l"(src))
#define CP_COMMIT() asm volatile("cp.async.commit_group;" ::: "memory")
#define CP_WAIT(n)  asm volatile("cp.async.wait_group %0;" :: "n"(n) : "memory")

// ldmatrix x4: 4 x (8x8 b16) tiles -> {kt.b0, kt.b1, kt+1.b0, kt+1.b1}
#define LDSM4(r, addr)                                                          \
    asm volatile("ldmatrix.sync.aligned.m8n8.x4.shared.b16 {%0,%1,%2,%3}, [%4];"\
                 : "=r"((r)[0]), "=r"((r)[1]), "=r"((r)[2]), "=r"((r)[3])       \
                 : "r"(addr))

// m16n8k16, fp16 accumulate: D/C = 2 b32 regs (2 adjacent cols per reg)
#define MMA16816H(d0,d1, a0,a1,a2,a3, b0,b1)                                    \
    asm volatile("mma.sync.aligned.m16n8k16.row.col.f16.f16.f16.f16 "           \
                 "{%0,%1}, {%2,%3,%4,%5}, {%6,%7}, {%0,%1};"                    \
                 : "+r"(d0), "+r"(d1)                                            \
                 : "r"(a0), "r"(a1), "r"(a2), "r"(a3), "r"(b0), "r"(b1))

// branch-free top-3 insert, fp32 (5 min/max)
#define INS3(t0, t1, t2, s) do {                 \
    float _m0 = fmaxf(t0, s), _l0 = fminf(t0, s);\
    float _m1 = fmaxf(t1, _l0), _l1 = fminf(t1, _l0); \
    t2 = fmaxf(t2, _l1); t1 = _m1; t0 = _m0;     \
} while (0)

// branch-free top-3 insert, half2 (2 independent streams per op)
#define INS3H(t0, t1, t2, s) do {                          \
    __half2 _m0 = __hmax2(t0, s), _l0 = __hmin2(t0, s);    \
    __half2 _m1 = __hmax2(t1, _l0), _l1 = __hmin2(t1, _l0);\
    t2 = __hmax2(t2, _l1); t1 = _m1; t0 = _m0;             \
} while (0)

__global__ void zero_out_kernel(float* out) {
    int i = threadIdx.x;
    if (i < BATCH * WAY) out[i] = 0.0f;
}

__global__ void __launch_bounds__(256) prep_q(const float* __restrict__ qf) {
    int q = blockIdx.x * 256 + threadIdx.x;
    int b = blockIdx.y;
    const float* src = qf + (size_t)b * DIM * NQ + q;
    float v[DIM]; float ss = 0.0f;
#pragma unroll
    for (int d = 0; d < DIM; ++d) { v[d] = src[(size_t)d * NQ]; ss = fmaf(v[d], v[d], ss); }
    float rn = 1.0f / fmaxf(sqrtf(ss), 1e-12f);
    uint4* dst = (uint4*)(g_qn + ((size_t)b * NQ + q) * DIM);
#pragma unroll
    for (int i = 0; i < 8; ++i) {
        uint32_t u[4];
#pragma unroll
        for (int j = 0; j < 4; ++j) {
            __half2 h = __float22half2_rn(make_float2(v[i*8 + j*2] * rn, v[i*8 + j*2 + 1] * rn));
            u[j] = *(uint32_t*)&h;
        }
        dst[i] = make_uint4(u[0], u[1], u[2], u[3]);
    }
}

__global__ void __launch_bounds__(256) prep_s(const float* __restrict__ sf) {
    int s = blockIdx.x * 256 + threadIdx.x;
    int w = blockIdx.y, b = blockIdx.z;
    size_t bw = (size_t)b * WAY + w;
    const float* src = sf + bw * DIM * NS + s;
    float v[DIM]; float ss = 0.0f;
#pragma unroll
    for (int d = 0; d < DIM; ++d) { v[d] = src[(size_t)d * NS]; ss = fmaf(v[d], v[d], ss); }
    float rn = 1.0f / fmaxf(sqrtf(ss), 1e-12f);
    uint4* dst = (uint4*)(g_sn + (bw * NS + s) * DIM);
#pragma unroll
    for (int i = 0; i < 8; ++i) {
        uint32_t u[4];
#pragma unroll
        for (int j = 0; j < 4; ++j) {
            __half2 h = __float22half2_rn(make_float2(v[i*8 + j*2] * rn, v[i*8 + j*2 + 1] * rn));
            u[j] = *(uint32_t*)&h;
        }
        dst[i] = make_uint4(u[0], u[1], u[2], u[3]);
    }
}

__global__ void __launch_bounds__(256, 4) knn_mma(float* __restrict__ out) {
    extern __shared__ char dsm[];
    __shared__ float red[4];
    __shared__ float xm[4][32][3];   // cross-warpN top-3 exchange: [warpM][row][k]

    const int tid  = threadIdx.x;
    const int lane = tid & 31;
    const int wid  = tid >> 5;
    const int warpM = wid & 3;        // 4 warps along M (32 rows each)
    const int warpN = wid >> 2;       // 2 warps along N (64 cols each)
    const int qt = blockIdx.x, w = blockIdx.y, b = blockIdx.z;

    const uint32_t sbase = smem_u32(dsm);
    const __half* Ag = g_qn + ((size_t)b * NQ + (size_t)qt * QTILE) * DIM;
    const __half* Sg = g_sn + (size_t)(b * WAY + w) * NS * DIM;

    // ---- stage A tile (128 x 64 fp16) via cp.async, group 0
#pragma unroll
    for (int i = 0; i < 4; ++i) {
        int idx = i * 256 + tid;            // 1024 16B segments
        int r = idx >> 3, seg = idx & 7;
        CP16(sbase + A_OFF + r * SROWB + seg * 16, Ag + r * DIM + seg * 8);
    }
    CP_COMMIT();
    // ---- stage S chunk 0 into buf 0, group 1
#pragma unroll
    for (int i = 0; i < 4; ++i) {
        int idx = i * 256 + tid;
        int r = idx >> 3, seg = idx & 7;
        CP16(sbase + B_OFF + r * SROWB + seg * 16, Sg + r * DIM + seg * 8);
    }
    CP_COMMIT();

    CP_WAIT(1);            // A tile ready
    __syncthreads();

    // ---- load A fragments to registers via ldmatrix: a[mt][kt][4]
    uint32_t a[2][4][4];
    {
        // rows: warpM*32 + mt*16 + (lane&15); seg: (lane>>4)*16B within 32B kt-pair
#pragma unroll
        for (int mt = 0; mt < 2; ++mt) {
            uint32_t rbase = sbase + A_OFF
                           + (uint32_t)(warpM * 32 + mt * 16 + (lane & 15)) * SROWB
                           + (uint32_t)(lane >> 4) * 16;
            // x4 tiles: {rows 0-7 seg0, rows 8-15 seg0, rows 0-7 seg1, rows 8-15 seg1}
            // = a-frag regs {r0, r1, r2, r3} for kt pair
            LDSM4(a[mt][0], rbase);            // kt0: k bytes 0..31
            LDSM4(a[mt][1], rbase + 32);       // kt1
            LDSM4(a[mt][2], rbase + 64);       // kt2
            LDSM4(a[mt][3], rbase + 96);       // kt3
        }
    }

    // half2 top-3 streams: t[r][k], r = (mt, rowhalf); halves = column-parity streams
    const __half2 NEGINF = __halves2half2(__ushort_as_half(0xFC00), __ushort_as_half(0xFC00));
    __half2 t[4][3];
#pragma unroll
    for (int r = 0; r < 4; ++r) { t[r][0] = NEGINF; t[r][1] = NEGINF; t[r][2] = NEGINF; }

    for (int ch = 0; ch < NCHUNK; ++ch) {
        const int cur = ch & 1;
        __syncthreads();   // all warps done with buffer cur^1 (previous chunk)
        if (ch + 1 < NCHUNK) {
            const __half* src = Sg + (size_t)(ch + 1) * SCHUNK * DIM;
            uint32_t dstb = sbase + B_OFF + (cur ^ 1) * BBUF;
#pragma unroll
            for (int i = 0; i < 4; ++i) {
                int idx = i * 256 + tid;
                int r = idx >> 3, seg = idx & 7;
                CP16(dstb + r * SROWB + seg * 16, src + r * DIM + seg * 8);
            }
            CP_COMMIT();
            CP_WAIT(1);    // chunk ch ready (ch+1 may be in flight)
        } else {
            CP_WAIT(0);
        }
        __syncthreads();

        // ldmatrix lane address base for B: row = s0 + (lane&7), seg = (lane>>3)*16B
        const uint32_t ldsm_base = sbase + B_OFF + cur * BBUF
                                 + (uint32_t)(warpN * 64 + (lane & 7)) * SROWB
                                 + (uint32_t)(lane >> 3) * 16;

        // 2 nt per body, 4 independent MMA chains; unroll 2 bodies for cross-iter overlap
#pragma unroll 2
        for (int nt = 0; nt < 8; nt += 2) {
            const uint32_t addr0 = ldsm_base + (uint32_t)(nt * 8) * SROWB;
            const uint32_t addr1 = addr0 + 8 * SROWB;
            uint32_t bA[4], bB[4], bC[4], bD[4];
            LDSM4(bA, addr0);        // nt+0: kt0, kt1
            LDSM4(bB, addr0 + 64);   // nt+0: kt2, kt3
            LDSM4(bC, addr1);        // nt+1: kt0, kt1
            LDSM4(bD, addr1 + 64);   // nt+1: kt2, kt3

            uint32_t d00 = 0, d01 = 0;   // nt+0, mt0
            uint32_t d02 = 0, d03 = 0;   // nt+0, mt1
            uint32_t d10 = 0, d11 = 0;   // nt+1, mt0
            uint32_t d12 = 0, d13 = 0;   // nt+1, mt1

            MMA16816H(d00, d01, a[0][0][0], a[0][0][1], a[0][0][2], a[0][0][3], bA[0], bA[1]);
            MMA16816H(d02, d03, a[1][0][0], a[1][0][1], a[1][0][2], a[1][0][3], bA[0], bA[1]);
            MMA16816H(d10, d11, a[0][0][0], a[0][0][1], a[0][0][2], a[0][0][3], bC[0], bC[1]);
            MMA16816H(d12, d13, a[1][0][0], a[1][0][1], a[1][0][2], a[1][0][3], bC[0], bC[1]);

            MMA16816H(d00, d01, a[0][1][0], a[0][1][1], a[0][1][2], a[0][1][3], bA[2], bA[3]);
            MMA16816H(d02, d03, a[1][1][0], a[1][1][1], a[1][1][2], a[1][1][3], bA[2], bA[3]);
            MMA16816H(d10, d11, a[0][1][0], a[0][1][1], a[0][1][2], a[0][1][3], bC[2], bC[3]);
            MMA16816H(d12, d13, a[1][1][0], a[1][1][1], a[1][1][2], a[1][1][3], bC[2], bC[3]);

            MMA16816H(d00, d01, a[0][2][0], a[0][2][1], a[0][2][2], a[0][2][3], bB[0], bB[1]);
            MMA16816H(d02, d03, a[1][2][0], a[1][2][1], a[1][2][2], a[1][2][3], bB[0], bB[1]);
            MMA16816H(d10, d11, a[0][2][0], a[0][2][1], a[0][2][2], a[0][2][3], bD[0], bD[1]);
            MMA16816H(d12, d13, a[1][2][0], a[1][2][1], a[1][2][2], a[1][2][3], bD[0], bD[1]);

            MMA16816H(d00, d01, a[0][3][0], a[0][3][1], a[0][3][2], a[0][3][3], bB[2], bB[3]);
            MMA16816H(d02, d03, a[1][3][0], a[1][3][1], a[1][3][2], a[1][3][3], bB[2], bB[3]);
            MMA16816H(d10, d11, a[0][3][0], a[0][3][1], a[0][3][2], a[0][3][3], bD[2], bD[3]);
            MMA16816H(d12, d13, a[1][3][0], a[1][3][1], a[1][3][2], a[1][3][3], bD[2], bD[3]);

            // D regs are half2 of adjacent columns: feed tournament directly
            INS3H(t[0][0], t[0][1], t[0][2], *(__half2*)&d00);
            INS3H(t[1][0], t[1][1], t[1][2], *(__half2*)&d01);
            INS3H(t[2][0], t[2][1], t[2][2], *(__half2*)&d02);
            INS3H(t[3][0], t[3][1], t[3][2], *(__half2*)&d03);
            INS3H(t[0][0], t[0][1], t[0][2], *(__half2*)&d10);
            INS3H(t[1][0], t[1][1], t[1][2], *(__half2*)&d11);
            INS3H(t[2][0], t[2][1], t[2][2], *(__half2*)&d12);
            INS3H(t[3][0], t[3][1], t[3][2], *(__half2*)&d13);
        }
    }

    // ---- merge top-3 across the 4 lanes (lane%4) that share each row (half2 domain)
#pragma unroll
    for (int r = 0; r < 4; ++r) {
#pragma unroll
        for (int d = 1; d <= 2; d <<= 1) {
            __half2 r0, r1, r2;
            *(uint32_t*)&r0 = __shfl_xor_sync(0xFFFFFFFFu, *(uint32_t*)&t[r][0], d);
            *(uint32_t*)&r1 = __shfl_xor_sync(0xFFFFFFFFu, *(uint32_t*)&t[r][1], d);
            *(uint32_t*)&r2 = __shfl_xor_sync(0xFFFFFFFFu, *(uint32_t*)&t[r][2], d);
            INS3H(t[r][0], t[r][1], t[r][2], r0);
            INS3H(t[r][0], t[r][1], t[r][2], r1);
            INS3H(t[r][0], t[r][1], t[r][2], r2);
        }
    }

    // ---- unpack halves (column-parity streams) and merge to per-row f32 top-3
    float f[4][3];
#pragma unroll
    for (int r = 0; r < 4; ++r) {
        f[r][0] = -1e30f; f[r][1] = -1e30f; f[r][2] = -1e30f;
#pragma unroll
        for (int k = 0; k < 3; ++k) {
            INS3(f[r][0], f[r][1], f[r][2], __low2float(t[r][k]));
            INS3(f[r][0], f[r][1], f[r][2], __high2float(t[r][k]));
        }
    }

    // ---- merge top-3 across warpN halves (each covered 512 of 1024 columns)
    const int gid = lane >> 2;
    if (warpN == 1 && (lane & 3) == 0) {
#pragma unroll
        for (int r = 0; r < 4; ++r) {
            int row = (r >> 1) * 16 + (r & 1) * 8 + gid;
            xm[warpM][row][0] = f[r][0];
            xm[warpM][row][1] = f[r][1];
            xm[warpM][row][2] = f[r][2];
        }
    }
    __syncthreads();

    if (warpN == 0) {
        float local = 0.0f;
        if ((lane & 3) == 0) {
#pragma unroll
            for (int r = 0; r < 4; ++r) {
                int row = (r >> 1) * 16 + (r & 1) * 8 + gid;
                INS3(f[r][0], f[r][1], f[r][2], xm[warpM][row][0]);
                INS3(f[r][0], f[r][1], f[r][2], xm[warpM][row][1]);
                INS3(f[r][0], f[r][1], f[r][2], xm[warpM][row][2]);
                local += f[r][0] + f[r][1] + f[r][2];
            }
        }
#pragma unroll
        for (int off = 16; off > 0; off >>= 1)
            local += __shfl_down_sync(0xFFFFFFFFu, local, off);
        if (lane == 0) red[warpM] = local;
    }
    __syncthreads();
    if (tid == 0) {
        atomicAdd(&out[b * WAY + w], red[0] + red[1] + red[2] + red[3]);
    }
}

extern "C" void kernel_launch(void* const* d_in, const int* in_sizes, int n_in,
                              void* d_out, int out_size) {
    const float* qf = (const float*)d_in[0];   // (64, 64, 32, 32)
    const float* sf = (const float*)d_in[1];   // (64, 5, 64, 1024)
    float* out = (float*)d_out;                // (64, 5)

    cudaFuncSetAttribute(knn_mma, cudaFuncAttributeMaxDynamicSharedMemorySize, SMEM_BYTES);

    zero_out_kernel<<<1, 512>>>(out);
    prep_q<<<dim3(NQ / 256, BATCH), 256>>>(qf);
    prep_s<<<dim3(NS / 256, WAY, BATCH), 256>>>(sf);
    knn_mma<<<dim3(NQ / QTILE, WAY, BATCH), 256, SMEM_BYTES>>>(out);
}

// round 8
// speedup vs baseline: 9.6435x; 1.0008x over previous
#include <cuda_runtime.h>
#include <cuda_fp16.h>
#include <cstdint>

#define BATCH 64
#define WAY   5
#define DIM   64
#define NQ    1024
#define NS    1024
#define QTILE 128
#define SCHUNK 128
#define NCHUNK (NS / SCHUNK)

// fp16 normalized scratch
__device__ __half g_qn[BATCH * NQ * DIM];          // [b][q][d]   8 MB
__device__ __half g_sn[BATCH * WAY * NS * DIM];    // [b][w][s][d] 40 MB

// smem layout (bytes): rows padded to 144B (72 halves) for conflict-free frag loads
#define SROWB 144
#define A_OFF 0
#define B_OFF (QTILE * SROWB)            // 18432
#define BBUF  (SCHUNK * SROWB)           // 18432
#define SMEM_BYTES (B_OFF + 2 * BBUF)    // 55296

__device__ __forceinline__ uint32_t smem_u32(const void* p) {
    uint32_t a;
    asm("{ .reg .u64 t; cvta.to.shared.u64 t, %1; cvt.u32.u64 %0, t; }" : "=r"(a) : "l"(p));
    return a;
}
#define CP16(dst, src) \
    asm volatile("cp.async.cg.shared.global [%0], [%1], 16;" :: "r"(dst), "l"(src))
#define CP_COMMIT() asm volatile("cp.async.commit_group;" ::: "memory")
#define CP_WAIT(n)  asm volatile("cp.async.wait_group %0;" :: "n"(n) : "memory")

// ldmatrix x4: 4 x (8x8 b16) tiles -> {kt.b0, kt.b1, kt+1.b0, kt+1.b1}
#define LDSM4(r, addr)                                                          \
    asm volatile("ldmatrix.sync.aligned.m8n8.x4.shared.b16 {%0,%1,%2,%3}, [%4];"\
                 : "=r"((r)[0]), "=r"((r)[1]), "=r"((r)[2]), "=r"((r)[3])       \
                 : "r"(addr))

// m16n8k16, fp16 accumulate: D/C = 2 b32 regs (2 adjacent cols per reg)
#define MMA16816H(d0,d1, a0,a1,a2,a3, b0,b1)                                    \
    asm volatile("mma.sync.aligned.m16n8k16.row.col.f16.f16.f16.f16 "           \
                 "{%0,%1}, {%2,%3,%4,%5}, {%6,%7}, {%0,%1};"                    \
                 : "+r"(d0), "+r"(d1)                                            \
                 : "r"(a0), "r"(a1), "r"(a2), "r"(a3), "r"(b0), "r"(b1))

// branch-free top-3 insert, fp32 (5 min/max)
#define INS3(t0, t1, t2, s) do {                 \
    float _m0 = fmaxf(t0, s), _l0 = fminf(t0, s);\
    float _m1 = fmaxf(t1, _l0), _l1 = fminf(t1, _l0); \
    t2 = fmaxf(t2, _l1); t1 = _m1; t0 = _m0;     \
} while (0)

// branch-free top-3 insert, half2 (2 independent streams per op)
#define INS3H(t0, t1, t2, s) do {                          \
    __half2 _m0 = __hmax2(t0, s), _l0 = __hmin2(t0, s);    \
    __half2 _m1 = __hmax2(t1, _l0), _l1 = __hmin2(t1, _l0);\
    t2 = __hmax2(t2, _l1); t1 = _m1; t0 = _m0;             \
} while (0)

__global__ void zero_out_kernel(float* out) {
    int i = threadIdx.x;
    if (i < BATCH * WAY) out[i] = 0.0f;
}

__global__ void __launch_bounds__(256) prep_q(const float* __restrict__ qf) {
    int q = blockIdx.x * 256 + threadIdx.x;
    int b = blockIdx.y;
    const float* src = qf + (size_t)b * DIM * NQ + q;
    float v[DIM]; float ss = 0.0f;
#pragma unroll
    for (int d = 0; d < DIM; ++d) { v[d] = src[(size_t)d * NQ]; ss = fmaf(v[d], v[d], ss); }
    float rn = 1.0f / fmaxf(sqrtf(ss), 1e-12f);
    uint4* dst = (uint4*)(g_qn + ((size_t)b * NQ + q) * DIM);
#pragma unroll
    for (int i = 0; i < 8; ++i) {
        uint32_t u[4];
#pragma unroll
        for (int j = 0; j < 4; ++j) {
            __half2 h = __float22half2_rn(make_float2(v[i*8 + j*2] * rn, v[i*8 + j*2 + 1] * rn));
            u[j] = *(uint32_t*)&h;
        }
        dst[i] = make_uint4(u[0], u[1], u[2], u[3]);
    }
}

__global__ void __launch_bounds__(256) prep_s(const float* __restrict__ sf) {
    int s = blockIdx.x * 256 + threadIdx.x;
    int w = blockIdx.y, b = blockIdx.z;
    size_t bw = (size_t)b * WAY + w;
    const float* src = sf + bw * DIM * NS + s;
    float v[DIM]; float ss = 0.0f;
#pragma unroll
    for (int d = 0; d < DIM; ++d) { v[d] = src[(size_t)d * NS]; ss = fmaf(v[d], v[d], ss); }
    float rn = 1.0f / fmaxf(sqrtf(ss), 1e-12f);
    uint4* dst = (uint4*)(g_sn + (bw * NS + s) * DIM);
#pragma unroll
    for (int i = 0; i < 8; ++i) {
        uint32_t u[4];
#pragma unroll
        for (int j = 0; j < 4; ++j) {
            __half2 h = __float22half2_rn(make_float2(v[i*8 + j*2] * rn, v[i*8 + j*2 + 1] * rn));
            u[j] = *(uint32_t*)&h;
        }
        dst[i] = make_uint4(u[0], u[1], u[2], u[3]);
    }
}

__global__ void __launch_bounds__(256, 3) knn_mma(float* __restrict__ out) {
    extern __shared__ char dsm[];
    __shared__ float red[4];
    __shared__ float xm[4][32][3];   // cross-warpN top-3 exchange: [warpM][row][k]

    const int tid  = threadIdx.x;
    const int lane = tid & 31;
    const int wid  = tid >> 5;
    const int warpM = wid & 3;        // 4 warps along M (32 rows each)
    const int warpN = wid >> 2;       // 2 warps along N (64 cols each)
    const int qt = blockIdx.x, w = blockIdx.y, b = blockIdx.z;

    const uint32_t sbase = smem_u32(dsm);
    const __half* Ag = g_qn + ((size_t)b * NQ + (size_t)qt * QTILE) * DIM;
    const __half* Sg = g_sn + (size_t)(b * WAY + w) * NS * DIM;

    // ---- stage A tile (128 x 64 fp16) via cp.async, group 0
#pragma unroll
    for (int i = 0; i < 4; ++i) {
        int idx = i * 256 + tid;            // 1024 16B segments
        int r = idx >> 3, seg = idx & 7;
        CP16(sbase + A_OFF + r * SROWB + seg * 16, Ag + r * DIM + seg * 8);
    }
    CP_COMMIT();
    // ---- stage S chunk 0 into buf 0, group 1
#pragma unroll
    for (int i = 0; i < 4; ++i) {
        int idx = i * 256 + tid;
        int r = idx >> 3, seg = idx & 7;
        CP16(sbase + B_OFF + r * SROWB + seg * 16, Sg + r * DIM + seg * 8);
    }
    CP_COMMIT();

    CP_WAIT(1);            // A tile ready
    __syncthreads();

    // ---- load A fragments to registers via ldmatrix: a[mt][kt][4]
    uint32_t a[2][4][4];
    {
#pragma unroll
        for (int mt = 0; mt < 2; ++mt) {
            uint32_t rbase = sbase + A_OFF
                           + (uint32_t)(warpM * 32 + mt * 16 + (lane & 15)) * SROWB
                           + (uint32_t)(lane >> 4) * 16;
            LDSM4(a[mt][0], rbase);            // kt0
            LDSM4(a[mt][1], rbase + 32);       // kt1
            LDSM4(a[mt][2], rbase + 64);       // kt2
            LDSM4(a[mt][3], rbase + 96);       // kt3
        }
    }

    // half2 top-3 streams: t[r][k], r = (mt, rowhalf); halves = column-parity streams
    const __half2 NEGINF = __halves2half2(__ushort_as_half(0xFC00), __ushort_as_half(0xFC00));
    __half2 t[4][3];
#pragma unroll
    for (int r = 0; r < 4; ++r) { t[r][0] = NEGINF; t[r][1] = NEGINF; t[r][2] = NEGINF; }

    for (int ch = 0; ch < NCHUNK; ++ch) {
        const int cur = ch & 1;
        __syncthreads();   // all warps done with buffer cur^1 (previous chunk)
        if (ch + 1 < NCHUNK) {
            const __half* src = Sg + (size_t)(ch + 1) * SCHUNK * DIM;
            uint32_t dstb = sbase + B_OFF + (cur ^ 1) * BBUF;
#pragma unroll
            for (int i = 0; i < 4; ++i) {
                int idx = i * 256 + tid;
                int r = idx >> 3, seg = idx & 7;
                CP16(dstb + r * SROWB + seg * 16, src + r * DIM + seg * 8);
            }
            CP_COMMIT();
            CP_WAIT(1);    // chunk ch ready (ch+1 may be in flight)
        } else {
            CP_WAIT(0);
        }
        __syncthreads();

        // ldmatrix lane address base for B: row = s0 + (lane&7), seg = (lane>>3)*16B
        const uint32_t ldsm_base = sbase + B_OFF + cur * BBUF
                                 + (uint32_t)(warpN * 64 + (lane & 7)) * SROWB
                                 + (uint32_t)(lane >> 3) * 16;

        // ---- software-pipelined nt loop: double-buffered B frags,
        //      LDSM of iteration i+1 issued before MMAs+tournament of i.
        uint32_t bf[2][4][4];   // [buf][{ntlo kt01, ntlo kt23, nthi kt01, nthi kt23}][4]
        LDSM4(bf[0][0], ldsm_base);
        LDSM4(bf[0][1], ldsm_base + 64);
        LDSM4(bf[0][2], ldsm_base + 8 * SROWB);
        LDSM4(bf[0][3], ldsm_base + 8 * SROWB + 64);

#pragma unroll
        for (int ntp = 0; ntp < 4; ++ntp) {
            const int pb = ntp & 1;
            if (ntp < 3) {
                const uint32_t na = ldsm_base + (uint32_t)((ntp + 1) * 16) * SROWB;
                LDSM4(bf[pb ^ 1][0], na);
                LDSM4(bf[pb ^ 1][1], na + 64);
                LDSM4(bf[pb ^ 1][2], na + 8 * SROWB);
                LDSM4(bf[pb ^ 1][3], na + 8 * SROWB + 64);
            }
            uint32_t (&bA)[4] = bf[pb][0];
            uint32_t (&bB)[4] = bf[pb][1];
            uint32_t (&bC)[4] = bf[pb][2];
            uint32_t (&bD)[4] = bf[pb][3];

            uint32_t d00 = 0, d01 = 0;   // ntlo, mt0
            uint32_t d02 = 0, d03 = 0;   // ntlo, mt1
            uint32_t d10 = 0, d11 = 0;   // nthi, mt0
            uint32_t d12 = 0, d13 = 0;   // nthi, mt1

            MMA16816H(d00, d01, a[0][0][0], a[0][0][1], a[0][0][2], a[0][0][3], bA[0], bA[1]);
            MMA16816H(d02, d03, a[1][0][0], a[1][0][1], a[1][0][2], a[1][0][3], bA[0], bA[1]);
            MMA16816H(d10, d11, a[0][0][0], a[0][0][1], a[0][0][2], a[0][0][3], bC[0], bC[1]);
            MMA16816H(d12, d13, a[1][0][0], a[1][0][1], a[1][0][2], a[1][0][3], bC[0], bC[1]);

            MMA16816H(d00, d01, a[0][1][0], a[0][1][1], a[0][1][2], a[0][1][3], bA[2], bA[3]);
            MMA16816H(d02, d03, a[1][1][0], a[1][1][1], a[1][1][2], a[1][1][3], bA[2], bA[3]);
            MMA16816H(d10, d11, a[0][1][0], a[0][1][1], a[0][1][2], a[0][1][3], bC[2], bC[3]);
            MMA16816H(d12, d13, a[1][1][0], a[1][1][1], a[1][1][2], a[1][1][3], bC[2], bC[3]);

            MMA16816H(d00, d01, a[0][2][0], a[0][2][1], a[0][2][2], a[0][2][3], bB[0], bB[1]);
            MMA16816H(d02, d03, a[1][2][0], a[1][2][1], a[1][2][2], a[1][2][3], bB[0], bB[1]);
            MMA16816H(d10, d11, a[0][2][0], a[0][2][1], a[0][2][2], a[0][2][3], bD[0], bD[1]);
            MMA16816H(d12, d13, a[1][2][0], a[1][2][1], a[1][2][2], a[1][2][3], bD[0], bD[1]);

            MMA16816H(d00, d01, a[0][3][0], a[0][3][1], a[0][3][2], a[0][3][3], bB[2], bB[3]);
            MMA16816H(d02, d03, a[1][3][0], a[1][3][1], a[1][3][2], a[1][3][3], bB[2], bB[3]);
            MMA16816H(d10, d11, a[0][3][0], a[0][3][1], a[0][3][2], a[0][3][3], bD[2], bD[3]);
            MMA16816H(d12, d13, a[1][3][0], a[1][3][1], a[1][3][2], a[1][3][3], bD[2], bD[3]);

            INS3H(t[0][0], t[0][1], t[0][2], *(__half2*)&d00);
            INS3H(t[1][0], t[1][1], t[1][2], *(__half2*)&d01);
            INS3H(t[2][0], t[2][1], t[2][2], *(__half2*)&d02);
            INS3H(t[3][0], t[3][1], t[3][2], *(__half2*)&d03);
            INS3H(t[0][0], t[0][1], t[0][2], *(__half2*)&d10);
            INS3H(t[1][0], t[1][1], t[1][2], *(__half2*)&d11);
            INS3H(t[2][0], t[2][1], t[2][2], *(__half2*)&d12);
            INS3H(t[3][0], t[3][1], t[3][2], *(__half2*)&d13);
        }
    }

    // ---- merge top-3 across the 4 lanes (lane%4) that share each row (half2 domain)
#pragma unroll
    for (int r = 0; r < 4; ++r) {
#pragma unroll
        for (int d = 1; d <= 2; d <<= 1) {
            __half2 r0, r1, r2;
            *(uint32_t*)&r0 = __shfl_xor_sync(0xFFFFFFFFu, *(uint32_t*)&t[r][0], d);
            *(uint32_t*)&r1 = __shfl_xor_sync(0xFFFFFFFFu, *(uint32_t*)&t[r][1], d);
            *(uint32_t*)&r2 = __shfl_xor_sync(0xFFFFFFFFu, *(uint32_t*)&t[r][2], d);
            INS3H(t[r][0], t[r][1], t[r][2], r0);
            INS3H(t[r][0], t[r][1], t[r][2], r1);
            INS3H(t[r][0], t[r][1], t[r][2], r2);
        }
    }

    // ---- unpack halves (column-parity streams) and merge to per-row f32 top-3
    float f[4][3];
#pragma unroll
    for (int r = 0; r < 4; ++r) {
        f[r][0] = -1e30f; f[r][1] = -1e30f; f[r][2] = -1e30f;
#pragma unroll
        for (int k = 0; k < 3; ++k) {
            INS3(f[r][0], f[r][1], f[r][2], __low2float(t[r][k]));
            INS3(f[r][0], f[r][1], f[r][2], __high2float(t[r][k]));
        }
    }

    // ---- merge top-3 across warpN halves (each covered 512 of 1024 columns)
    const int gid = lane >> 2;
    if (warpN == 1 && (lane & 3) == 0) {
#pragma unroll
        for (int r = 0; r < 4; ++r) {
            int row = (r >> 1) * 16 + (r & 1) * 8 + gid;
            xm[warpM][row][0] = f[r][0];
            xm[warpM][row][1] = f[r][1];
            xm[warpM][row][2] = f[r][2];
        }
    }
    __syncthreads();

    if (warpN == 0) {
        float local = 0.0f;
        if ((lane & 3) == 0) {
#pragma unroll
            for (int r = 0; r < 4; ++r) {
                int row = (r >> 1) * 16 + (r & 1) * 8 + gid;
                INS3(f[r][0], f[r][1], f[r][2], xm[warpM][row][0]);
                INS3(f[r][0], f[r][1], f[r][2], xm[warpM][row][1]);
                INS3(f[r][0], f[r][1], f[r][2], xm[warpM][row][2]);
                local += f[r][0] + f[r][1] + f[r][2];
            }
        }
#pragma unroll
        for (int off = 16; off > 0; off >>= 1)
            local += __shfl_down_sync(0xFFFFFFFFu, local, off);
        if (lane == 0) red[warpM] = local;
    }
    __syncthreads();
    if (tid == 0) {
        atomicAdd(&out[b * WAY + w], red[0] + red[1] + red[2] + red[3]);
    }
}

extern "C" void kernel_launch(void* const* d_in, const int* in_sizes, int n_in,
                              void* d_out, int out_size) {
    const float* qf = (const float*)d_in[0];   // (64, 64, 32, 32)
    const float* sf = (const float*)d_in[1];   // (64, 5, 64, 1024)
    float* out = (float*)d_out;                // (64, 5)

    cudaFuncSetAttribute(knn_mma, cudaFuncAttributeMaxDynamicSharedMemorySize, SMEM_BYTES);

    zero_out_kernel<<<1, 512>>>(out);
    prep_q<<<dim3(NQ / 256, BATCH), 256>>>(qf);
    prep_s<<<dim3(NS / 256, WAY, BATCH), 256>>>(sf);
    knn_mma<<<dim3(NQ / QTILE, WAY, BATCH), 256, SMEM_BYTES>>>(out);
}

// round 9
// speedup vs baseline: 9.8615x; 1.0226x over previous
#include <cuda_runtime.h>
#include <cuda_fp16.h>
#include <cstdint>

#define BATCH 64
#define WAY   5
#define DIM   64
#define NQ    1024
#define NS    1024
#define QTILE 128
#define SCHUNK 128
#define NCHUNK (NS / SCHUNK)
#define NTILES (BATCH * WAY * (NQ / QTILE))   // 2560
#define PGRID  592                             // 148 SMs x 4 CTAs

// fp16 normalized scratch
__device__ __half g_qn[BATCH * NQ * DIM];          // [b][q][d]   8 MB
__device__ __half g_sn[BATCH * WAY * NS * DIM];    // [b][w][s][d] 40 MB
__device__ unsigned g_ticket;

// smem layout (bytes): rows padded to 144B (72 halves) for conflict-free frag loads
#define SROWB 144
#define A_OFF 0
#define B_OFF (QTILE * SROWB)            // 18432
#define BBUF  (SCHUNK * SROWB)           // 18432
#define SMEM_BYTES (B_OFF + 2 * BBUF)    // 55296

__device__ __forceinline__ uint32_t smem_u32(const void* p) {
    uint32_t a;
    asm("{ .reg .u64 t; cvta.to.shared.u64 t, %1; cvt.u32.u64 %0, t; }" : "=r"(a) : "l"(p));
    return a;
}
#define CP16(dst, src) \
    asm volatile("cp.async.cg.shared.global [%0], [%1], 16;" :: "r"(dst), "l"(src))
#define CP_COMMIT() asm volatile("cp.async.commit_group;" ::: "memory")
#define CP_WAIT(n)  asm volatile("cp.async.wait_group %0;" :: "n"(n) : "memory")

#define LDSM4(r, addr)                                                          \
    asm volatile("ldmatrix.sync.aligned.m8n8.x4.shared.b16 {%0,%1,%2,%3}, [%4];"\
                 : "=r"((r)[0]), "=r"((r)[1]), "=r"((r)[2]), "=r"((r)[3])       \
                 : "r"(addr))

#define MMA16816H(d0,d1, a0,a1,a2,a3, b0,b1)                                    \
    asm volatile("mma.sync.aligned.m16n8k16.row.col.f16.f16.f16.f16 "           \
                 "{%0,%1}, {%2,%3,%4,%5}, {%6,%7}, {%0,%1};"                    \
                 : "+r"(d0), "+r"(d1)                                            \
                 : "r"(a0), "r"(a1), "r"(a2), "r"(a3), "r"(b0), "r"(b1))

#define INS3(t0, t1, t2, s) do {                 \
    float _m0 = fmaxf(t0, s), _l0 = fminf(t0, s);\
    float _m1 = fmaxf(t1, _l0), _l1 = fminf(t1, _l0); \
    t2 = fmaxf(t2, _l1); t1 = _m1; t0 = _m0;     \
} while (0)

#define INS3H(t0, t1, t2, s) do {                          \
    __half2 _m0 = __hmax2(t0, s), _l0 = __hmin2(t0, s);    \
    __half2 _m1 = __hmax2(t1, _l0), _l1 = __hmin2(t1, _l0);\
    t2 = __hmax2(t2, _l1); t1 = _m1; t0 = _m0;             \
} while (0)

// ---- fused setup: zero out, reset ticket, normalize Q and S into fp16 scratch
__global__ void __launch_bounds__(256) prep_all(const float* __restrict__ qf,
                                                const float* __restrict__ sf,
                                                float* __restrict__ out) {
    const int blk = blockIdx.x;
    const int tid = threadIdx.x;
    if (blk == 0 && tid == 0) g_ticket = 0;
    if (blk < 2) {
        int i = blk * 256 + tid;
        if (i < BATCH * WAY) out[i] = 0.0f;
    }
    if (blk < 256) {
        // Q part: 4 blocks per batch
        int q = (blk & 3) * 256 + tid;
        int b = blk >> 2;
        const float* src = qf + (size_t)b * DIM * NQ + q;
        float v[DIM]; float ss = 0.0f;
#pragma unroll
        for (int d = 0; d < DIM; ++d) { v[d] = src[(size_t)d * NQ]; ss = fmaf(v[d], v[d], ss); }
        float rn = 1.0f / fmaxf(sqrtf(ss), 1e-12f);
        uint4* dst = (uint4*)(g_qn + ((size_t)b * NQ + q) * DIM);
#pragma unroll
        for (int i = 0; i < 8; ++i) {
            uint32_t u[4];
#pragma unroll
            for (int j = 0; j < 4; ++j) {
                __half2 h = __float22half2_rn(make_float2(v[i*8 + j*2] * rn, v[i*8 + j*2 + 1] * rn));
                u[j] = *(uint32_t*)&h;
            }
            dst[i] = make_uint4(u[0], u[1], u[2], u[3]);
        }
    } else {
        // S part: 1280 blocks = 4 s-chunks x 5 ways x 64 batches
        int sb = blk - 256;
        int s = (sb & 3) * 256 + tid;
        int w = (sb >> 2) % WAY;
        int b = (sb >> 2) / WAY;
        size_t bw = (size_t)b * WAY + w;
        const float* src = sf + bw * DIM * NS + s;
        float v[DIM]; float ss = 0.0f;
#pragma unroll
        for (int d = 0; d < DIM; ++d) { v[d] = src[(size_t)d * NS]; ss = fmaf(v[d], v[d], ss); }
        float rn = 1.0f / fmaxf(sqrtf(ss), 1e-12f);
        uint4* dst = (uint4*)(g_sn + (bw * NS + s) * DIM);
#pragma unroll
        for (int i = 0; i < 8; ++i) {
            uint32_t u[4];
#pragma unroll
            for (int j = 0; j < 4; ++j) {
                __half2 h = __float22half2_rn(make_float2(v[i*8 + j*2] * rn, v[i*8 + j*2 + 1] * rn));
                u[j] = *(uint32_t*)&h;
            }
            dst[i] = make_uint4(u[0], u[1], u[2], u[3]);
        }
    }
}

__global__ void __launch_bounds__(256, 4) knn_mma(float* __restrict__ out) {
    extern __shared__ char dsm[];
    __shared__ float red[4];
    __shared__ float xm[4][32][3];   // cross-warpN top-3 exchange
    __shared__ unsigned s_tile;

    const int tid  = threadIdx.x;
    const int lane = tid & 31;
    const int wid  = tid >> 5;
    const int warpM = wid & 3;        // 4 warps along M (32 rows each)
    const int warpN = wid >> 2;       // 2 warps along N (64 cols each)

    const uint32_t sbase = smem_u32(dsm);

    while (true) {
        if (tid == 0) s_tile = atomicAdd(&g_ticket, 1u);
        __syncthreads();
        const unsigned tile = s_tile;
        if (tile >= NTILES) break;

        const int qt = tile & 7;             // qt fastest: concurrent tiles share S in L2
        const int bw = tile >> 3;
        const int w  = bw % WAY;
        const int b  = bw / WAY;

        const __half* Ag = g_qn + ((size_t)b * NQ + (size_t)qt * QTILE) * DIM;
        const __half* Sg = g_sn + (size_t)(b * WAY + w) * NS * DIM;

        // ---- stage A tile (128 x 64 fp16) via cp.async, group 0
#pragma unroll
        for (int i = 0; i < 4; ++i) {
            int idx = i * 256 + tid;
            int r = idx >> 3, seg = idx & 7;
            CP16(sbase + A_OFF + r * SROWB + seg * 16, Ag + r * DIM + seg * 8);
        }
        CP_COMMIT();
        // ---- stage S chunk 0 into buf 0, group 1
#pragma unroll
        for (int i = 0; i < 4; ++i) {
            int idx = i * 256 + tid;
            int r = idx >> 3, seg = idx & 7;
            CP16(sbase + B_OFF + r * SROWB + seg * 16, Sg + r * DIM + seg * 8);
        }
        CP_COMMIT();

        CP_WAIT(1);            // A tile ready
        __syncthreads();

        // ---- A fragments via ldmatrix: a[mt][kt][4]
        uint32_t a[2][4][4];
#pragma unroll
        for (int mt = 0; mt < 2; ++mt) {
            uint32_t rbase = sbase + A_OFF
                           + (uint32_t)(warpM * 32 + mt * 16 + (lane & 15)) * SROWB
                           + (uint32_t)(lane >> 4) * 16;
            LDSM4(a[mt][0], rbase);
            LDSM4(a[mt][1], rbase + 32);
            LDSM4(a[mt][2], rbase + 64);
            LDSM4(a[mt][3], rbase + 96);
        }

        const __half2 NEGINF = __halves2half2(__ushort_as_half(0xFC00), __ushort_as_half(0xFC00));
        __half2 t[4][3];
#pragma unroll
        for (int r = 0; r < 4; ++r) { t[r][0] = NEGINF; t[r][1] = NEGINF; t[r][2] = NEGINF; }

        for (int ch = 0; ch < NCHUNK; ++ch) {
            const int cur = ch & 1;
            __syncthreads();   // all warps done with buffer cur^1
            if (ch + 1 < NCHUNK) {
                const __half* src = Sg + (size_t)(ch + 1) * SCHUNK * DIM;
                uint32_t dstb = sbase + B_OFF + (cur ^ 1) * BBUF;
#pragma unroll
                for (int i = 0; i < 4; ++i) {
                    int idx = i * 256 + tid;
                    int r = idx >> 3, seg = idx & 7;
                    CP16(dstb + r * SROWB + seg * 16, src + r * DIM + seg * 8);
                }
                CP_COMMIT();
                CP_WAIT(1);
            } else {
                CP_WAIT(0);
            }
            __syncthreads();

            const uint32_t ldsm_base = sbase + B_OFF + cur * BBUF
                                     + (uint32_t)(warpN * 64 + (lane & 7)) * SROWB
                                     + (uint32_t)(lane >> 3) * 16;

#pragma unroll 2
            for (int nt = 0; nt < 8; nt += 2) {
                const uint32_t addr0 = ldsm_base + (uint32_t)(nt * 8) * SROWB;
                const uint32_t addr1 = addr0 + 8 * SROWB;
                uint32_t bA[4], bB[4], bC[4], bD[4];
                LDSM4(bA, addr0);        // nt+0: kt0, kt1
                LDSM4(bB, addr0 + 64);   // nt+0: kt2, kt3
                LDSM4(bC, addr1);        // nt+1: kt0, kt1
                LDSM4(bD, addr1 + 64);   // nt+1: kt2, kt3

                uint32_t d00 = 0, d01 = 0, d02 = 0, d03 = 0;
                uint32_t d10 = 0, d11 = 0, d12 = 0, d13 = 0;

                MMA16816H(d00, d01, a[0][0][0], a[0][0][1], a[0][0][2], a[0][0][3], bA[0], bA[1]);
                MMA16816H(d02, d03, a[1][0][0], a[1][0][1], a[1][0][2], a[1][0][3], bA[0], bA[1]);
                MMA16816H(d10, d11, a[0][0][0], a[0][0][1], a[0][0][2], a[0][0][3], bC[0], bC[1]);
                MMA16816H(d12, d13, a[1][0][0], a[1][0][1], a[1][0][2], a[1][0][3], bC[0], bC[1]);

                MMA16816H(d00, d01, a[0][1][0], a[0][1][1], a[0][1][2], a[0][1][3], bA[2], bA[3]);
                MMA16816H(d02, d03, a[1][1][0], a[1][1][1], a[1][1][2], a[1][1][3], bA[2], bA[3]);
                MMA16816H(d10, d11, a[0][1][0], a[0][1][1], a[0][1][2], a[0][1][3], bC[2], bC[3]);
                MMA16816H(d12, d13, a[1][1][0], a[1][1][1], a[1][1][2], a[1][1][3], bC[2], bC[3]);

                MMA16816H(d00, d01, a[0][2][0], a[0][2][1], a[0][2][2], a[0][2][3], bB[0], bB[1]);
                MMA16816H(d02, d03, a[1][2][0], a[1][2][1], a[1][2][2], a[1][2][3], bB[0], bB[1]);
                MMA16816H(d10, d11, a[0][2][0], a[0][2][1], a[0][2][2], a[0][2][3], bD[0], bD[1]);
                MMA16816H(d12, d13, a[1][2][0], a[1][2][1], a[1][2][2], a[1][2][3], bD[0], bD[1]);

                MMA16816H(d00, d01, a[0][3][0], a[0][3][1], a[0][3][2], a[0][3][3], bB[2], bB[3]);
                MMA16816H(d02, d03, a[1][3][0], a[1][3][1], a[1][3][2], a[1][3][3], bB[2], bB[3]);
                MMA16816H(d10, d11, a[0][3][0], a[0][3][1], a[0][3][2], a[0][3][3], bD[2], bD[3]);
                MMA16816H(d12, d13, a[1][3][0], a[1][3][1], a[1][3][2], a[1][3][3], bD[2], bD[3]);

                INS3H(t[0][0], t[0][1], t[0][2], *(__half2*)&d00);
                INS3H(t[1][0], t[1][1], t[1][2], *(__half2*)&d01);
                INS3H(t[2][0], t[2][1], t[2][2], *(__half2*)&d02);
                INS3H(t[3][0], t[3][1], t[3][2], *(__half2*)&d03);
                INS3H(t[0][0], t[0][1], t[0][2], *(__half2*)&d10);
                INS3H(t[1][0], t[1][1], t[1][2], *(__half2*)&d11);
                INS3H(t[2][0], t[2][1], t[2][2], *(__half2*)&d12);
                INS3H(t[3][0], t[3][1], t[3][2], *(__half2*)&d13);
            }
        }

        // ---- merge top-3 across the 4 lanes sharing each row (half2 domain)
#pragma unroll
        for (int r = 0; r < 4; ++r) {
#pragma unroll
            for (int d = 1; d <= 2; d <<= 1) {
                __half2 r0, r1, r2;
                *(uint32_t*)&r0 = __shfl_xor_sync(0xFFFFFFFFu, *(uint32_t*)&t[r][0], d);
                *(uint32_t*)&r1 = __shfl_xor_sync(0xFFFFFFFFu, *(uint32_t*)&t[r][1], d);
                *(uint32_t*)&r2 = __shfl_xor_sync(0xFFFFFFFFu, *(uint32_t*)&t[r][2], d);
                INS3H(t[r][0], t[r][1], t[r][2], r0);
                INS3H(t[r][0], t[r][1], t[r][2], r1);
                INS3H(t[r][0], t[r][1], t[r][2], r2);
            }
        }

        // ---- unpack column-parity streams, merge to per-row f32 top-3
        float f[4][3];
#pragma unroll
        for (int r = 0; r < 4; ++r) {
            f[r][0] = -1e30f; f[r][1] = -1e30f; f[r][2] = -1e30f;
#pragma unroll
            for (int k = 0; k < 3; ++k) {
                INS3(f[r][0], f[r][1], f[r][2], __low2float(t[r][k]));
                INS3(f[r][0], f[r][1], f[r][2], __high2float(t[r][k]));
            }
        }

        // ---- merge across warpN halves
        const int gid = lane >> 2;
        if (warpN == 1 && (lane & 3) == 0) {
#pragma unroll
            for (int r = 0; r < 4; ++r) {
                int row = (r >> 1) * 16 + (r & 1) * 8 + gid;
                xm[warpM][row][0] = f[r][0];
                xm[warpM][row][1] = f[r][1];
                xm[warpM][row][2] = f[r][2];
            }
        }
        __syncthreads();

        if (warpN == 0) {
            float local = 0.0f;
            if ((lane & 3) == 0) {
#pragma unroll
                for (int r = 0; r < 4; ++r) {
                    int row = (r >> 1) * 16 + (r & 1) * 8 + gid;
                    INS3(f[r][0], f[r][1], f[r][2], xm[warpM][row][0]);
                    INS3(f[r][0], f[r][1], f[r][2], xm[warpM][row][1]);
                    INS3(f[r][0], f[r][1], f[r][2], xm[warpM][row][2]);
                    local += f[r][0] + f[r][1] + f[r][2];
                }
            }
#pragma unroll
            for (int off = 16; off > 0; off >>= 1)
                local += __shfl_down_sync(0xFFFFFFFFu, local, off);
            if (lane == 0) red[warpM] = local;
        }
        __syncthreads();
        if (tid == 0) {
            atomicAdd(&out[b * WAY + w], red[0] + red[1] + red[2] + red[3]);
        }
        __syncthreads();   // protect red/xm/s_tile before next iteration
    }
}

extern "C" void kernel_launch(void* const* d_in, const int* in_sizes, int n_in,
                              void* d_out, int out_size) {
    const float* qf = (const float*)d_in[0];   // (64, 64, 32, 32)
    const float* sf = (const float*)d_in[1];   // (64, 5, 64, 1024)
    float* out = (float*)d_out;                // (64, 5)

    cudaFuncSetAttribute(knn_mma, cudaFuncAttributeMaxDynamicSharedMemorySize, SMEM_BYTES);

    prep_all<<<1536, 256>>>(qf, sf, out);
    knn_mma<<<PGRID, 256, SMEM_BYTES>>>(out);
}